// round 2
// baseline (speedup 1.0000x reference)
#include <cuda_runtime.h>
#include <cstdint>

// Problem constants (fixed shapes for this problem instance)
#define N_NODES 50000
#define DIM     64
#define CHUNKS  (DIM / 4)   // float4 chunks per row = 16

// Scratch: M_v accumulator [N_NODES, DIM] float32 = 12.8 MB (L2-resident).
// Declared as float4 so the base is guaranteed 16B-aligned for red.v4.f32.
__device__ float4 g_Mv[(size_t)N_NODES * CHUNKS];

// 1 = indices stored as int64, 0 = indices stored as int32.
__device__ int g_is64;

// ---------------------------------------------------------------------------
// Index load helper: branch on the uniform dtype flag.
// ---------------------------------------------------------------------------
__device__ __forceinline__ long long load_idx(const void* base, long long i, int is64) {
    if (is64) return __ldg(((const long long*)base) + i);
    return (long long)__ldg(((const int*)base) + i);
}

// ---------------------------------------------------------------------------
// Kernel 1: zero the accumulator + dtype probe (thread 0 of block 0).
// Probe: read first 64 entries of rev_index as int64; if any is outside
// [0, E), the storage must be int32 (two fused 32-bit indices are >= 2^32
// with overwhelming probability).
// ---------------------------------------------------------------------------
__global__ void zero_and_probe_kernel(int n4, const void* rev, int E) {
    int i = blockIdx.x * blockDim.x + threadIdx.x;
    if (i < n4) {
        g_Mv[i] = make_float4(0.f, 0.f, 0.f, 0.f);
    }
    if (i == 0) {
        const long long* r64 = (const long long*)rev;
        int ok = 1;
        int n = (E < 64) ? E : 64;
        for (int k = 0; k < n; k++) {
            long long v = r64[k];
            if (v < 0 || v >= (long long)E) { ok = 0; break; }
        }
        g_is64 = ok;
    }
}

// ---------------------------------------------------------------------------
// Kernel 2: scatter-add edge messages into destination nodes.
// Thread t handles edge e = t/16, chunk c = t%16 (one float4).
// Consecutive threads read consecutive float4s of M -> fully coalesced.
// red.global.add.v4.f32: one L2-side reduction per 16B, no return value.
// ---------------------------------------------------------------------------
__global__ void scatter_kernel(const float4* __restrict__ M4,
                               const void* __restrict__ ei,
                               int E) {
    int t = blockIdx.x * blockDim.x + threadIdx.x;
    int e = t >> 4;
    int c = t & 15;
    if (e >= E) return;

    int is64 = g_is64;
    long long d = load_idx(ei, (long long)E + e, is64);   // edge_index[1][e]
    float4 v = __ldg(&M4[(size_t)e * CHUNKS + c]);

    float4* p = &g_Mv[(size_t)d * CHUNKS + c];
    asm volatile(
        "red.global.add.v4.f32 [%0], {%1, %2, %3, %4};"
        :: "l"(__cvta_generic_to_global(p)),
           "f"(v.x), "f"(v.y), "f"(v.z), "f"(v.w)
        : "memory");
}

// ---------------------------------------------------------------------------
// Kernel 3: out[e] = M_v[src[e]] - M[rev[e]]   (per float4 chunk)
// M_v gather hits L2 (12.8MB resident); M[rev] gather covers whole 256B rows
// with 16 consecutive threads -> 2 complete 128B lines per row.
// ---------------------------------------------------------------------------
__global__ void gather_kernel(const float4* __restrict__ M4,
                              const void* __restrict__ ei,
                              const void* __restrict__ rev,
                              float4* __restrict__ out,
                              int E) {
    int t = blockIdx.x * blockDim.x + threadIdx.x;
    int e = t >> 4;
    int c = t & 15;
    if (e >= E) return;

    int is64 = g_is64;
    long long s = load_idx(ei, e, is64);        // edge_index[0][e]
    long long r = load_idx(rev, e, is64);       // rev_index[e]

    float4 a = __ldg(&g_Mv[(size_t)s * CHUNKS + c]);
    float4 b = __ldg(&M4[(size_t)r * CHUNKS + c]);

    float4 o;
    o.x = a.x - b.x;
    o.y = a.y - b.y;
    o.z = a.z - b.z;
    o.w = a.w - b.w;
    out[(size_t)e * CHUNKS + c] = o;
}

// ---------------------------------------------------------------------------
// Launcher. Inputs (metadata order):
//   d_in[0] = M          float32       [E, 64]
//   d_in[1] = edge_index int64/int32   [2, E]   (row 0 = src, row 1 = dest)
//   d_in[2] = rev_index  int64/int32   [E]
//   d_in[3] = dim_size   scalar (fixed 50000, unused)
// Output: float32 [E, 64]
// ---------------------------------------------------------------------------
extern "C" void kernel_launch(void* const* d_in, const int* in_sizes, int n_in,
                              void* d_out, int out_size) {
    const float4* M4   = (const float4*)d_in[0];
    const void*   ei   = d_in[1];
    const void*   rev  = d_in[2];
    float4*       out4 = (float4*)d_out;

    const int E = in_sizes[2];    // rev_index element count

    // 1) zero accumulator + dtype probe
    {
        int n4 = N_NODES * CHUNKS;            // 800,000 float4s
        int tpb = 256;
        int blocks = (n4 + tpb - 1) / tpb;
        zero_and_probe_kernel<<<blocks, tpb>>>(n4, rev, E);
    }

    // 2) scatter-add
    {
        long long threads = (long long)E * CHUNKS;
        int tpb = 256;
        int blocks = (int)((threads + tpb - 1) / tpb);
        scatter_kernel<<<blocks, tpb>>>(M4, ei, E);
    }

    // 3) gather + subtract
    {
        long long threads = (long long)E * CHUNKS;
        int tpb = 256;
        int blocks = (int)((threads + tpb - 1) / tpb);
        gather_kernel<<<blocks, tpb>>>(M4, ei, rev, out4, E);
    }
}

// round 3
// speedup vs baseline: 1.1883x; 1.1883x over previous
#include <cuda_runtime.h>
#include <cstdint>

#define N_NODES 50000
#define DIM     64
#define CHUNKS  (DIM / 4)    // 16 float4 per row
#define TPE     8            // threads per edge (each handles 2 float4s)

// Accumulator [N_NODES, 16] float4 = 12.8 MB (L2-resident). float4 => 16B aligned.
__device__ float4 g_Mv[(size_t)N_NODES * CHUNKS];

// 1 = indices stored as int64, 0 = int32
__device__ int g_is64;

__device__ __forceinline__ long long load_idx(const void* base, long long i, int is64) {
    if (is64) return __ldg(((const long long*)base) + i);
    return (long long)__ldg(((const int*)base) + i);
}

// ---------------------------------------------------------------------------
// Kernel 1: zero accumulator + index-dtype probe (thread 0).
// ---------------------------------------------------------------------------
__global__ void zero_and_probe_kernel(int n4, const void* rev, int E) {
    int i = blockIdx.x * blockDim.x + threadIdx.x;
    if (i < n4) g_Mv[i] = make_float4(0.f, 0.f, 0.f, 0.f);
    if (i == 0) {
        const long long* r64 = (const long long*)rev;
        int ok = 1;
        int n = (E < 64) ? E : 64;
        for (int k = 0; k < n; k++) {
            long long v = r64[k];
            if (v < 0 || v >= (long long)E) { ok = 0; break; }
        }
        g_is64 = ok;
    }
}

// ---------------------------------------------------------------------------
// Kernel 2: scatter-add. 8 threads/edge, 2 float4 chunks each.
// M read: evict-normal (leaves tail of M resident in L2 for the gather's
// random M[rev] reads). RED.v4: one 16B L2-side reduction per chunk.
// ---------------------------------------------------------------------------
__global__ void scatter_kernel(const float4* __restrict__ M4,
                               const void* __restrict__ ei,
                               int E) {
    int t = blockIdx.x * blockDim.x + threadIdx.x;
    int e = t >> 3;          // edge
    int c = t & 7;           // chunk 0..7 (also handles c+8)
    if (e >= E) return;

    int is64 = g_is64;
    long long d = load_idx(ei, (long long)E + e, is64);   // dest

    const float4* mrow = M4 + (size_t)e * CHUNKS;
    float4 v0 = __ldg(&mrow[c]);
    float4 v1 = __ldg(&mrow[c + 8]);

    float4* prow = g_Mv + (size_t)d * CHUNKS;
    asm volatile("red.global.add.v4.f32 [%0], {%1, %2, %3, %4};"
        :: "l"(__cvta_generic_to_global(prow + c)),
           "f"(v0.x), "f"(v0.y), "f"(v0.z), "f"(v0.w) : "memory");
    asm volatile("red.global.add.v4.f32 [%0], {%1, %2, %3, %4};"
        :: "l"(__cvta_generic_to_global(prow + c + 8)),
           "f"(v1.x), "f"(v1.y), "f"(v1.z), "f"(v1.w) : "memory");
}

// ---------------------------------------------------------------------------
// Kernel 3: out[e] = M_v[src[e]] - M[rev[e]]. 8 threads/edge, 2 chunks each.
// M_v: evict-normal (keep 12.8MB resident -> pure L2 hits).
// M[rev]: evict-first streaming load (no L2 pollution; still hits scatter's
//         leftover residency). out: evict-first streaming store.
// ---------------------------------------------------------------------------
__global__ void gather_kernel(const float4* __restrict__ M4,
                              const void* __restrict__ ei,
                              const void* __restrict__ rev,
                              float4* __restrict__ out,
                              int E) {
    int t = blockIdx.x * blockDim.x + threadIdx.x;
    int e = t >> 3;
    int c = t & 7;
    if (e >= E) return;

    int is64 = g_is64;
    long long s = load_idx(ei, e, is64);       // src
    long long r = load_idx(rev, e, is64);      // rev

    const float4* arow = g_Mv + (size_t)s * CHUNKS;
    const float4* brow = M4 + (size_t)r * CHUNKS;

    float4 a0 = __ldg(&arow[c]);
    float4 a1 = __ldg(&arow[c + 8]);
    float4 b0 = __ldcs(&brow[c]);
    float4 b1 = __ldcs(&brow[c + 8]);

    float4 o0, o1;
    o0.x = a0.x - b0.x; o0.y = a0.y - b0.y; o0.z = a0.z - b0.z; o0.w = a0.w - b0.w;
    o1.x = a1.x - b1.x; o1.y = a1.y - b1.y; o1.z = a1.z - b1.z; o1.w = a1.w - b1.w;

    float4* orow = out + (size_t)e * CHUNKS;
    __stcs(&orow[c], o0);
    __stcs(&orow[c + 8], o1);
}

// ---------------------------------------------------------------------------
// Launcher. Inputs (metadata order):
//   d_in[0] = M          float32     [E, 64]
//   d_in[1] = edge_index int64/int32 [2, E]  (row0=src, row1=dest)
//   d_in[2] = rev_index  int64/int32 [E]
//   d_in[3] = dim_size   scalar (50000, unused)
// Output: float32 [E, 64]
// ---------------------------------------------------------------------------
extern "C" void kernel_launch(void* const* d_in, const int* in_sizes, int n_in,
                              void* d_out, int out_size) {
    const float4* M4   = (const float4*)d_in[0];
    const void*   ei   = d_in[1];
    const void*   rev  = d_in[2];
    float4*       out4 = (float4*)d_out;

    const int E = in_sizes[2];

    {
        int n4 = N_NODES * CHUNKS;
        int tpb = 256;
        zero_and_probe_kernel<<<(n4 + tpb - 1) / tpb, tpb>>>(n4, rev, E);
    }
    {
        long long threads = (long long)E * TPE;
        int tpb = 256;
        int blocks = (int)((threads + tpb - 1) / tpb);
        scatter_kernel<<<blocks, tpb>>>(M4, ei, E);
    }
    {
        long long threads = (long long)E * TPE;
        int tpb = 256;
        int blocks = (int)((threads + tpb - 1) / tpb);
        gather_kernel<<<blocks, tpb>>>(M4, ei, rev, out4, E);
    }
}